// round 2
// baseline (speedup 1.0000x reference)
#include <cuda_runtime.h>
#include <math.h>

// ---------------------------------------------------------------------------
// PANEmbLossV1 — B x (D,H,W) embedding loss with L=32 labels.
// Pipeline: zero -> accum (cnt, cnt_k, sum_k) -> means -> agg pass (sum_v)
//           -> finalize (agg + dis + reg per batch).
// ---------------------------------------------------------------------------

#define LBL 32
#define MAXB 8
#define MAXD 4
#define DELTA_AGG 0.5f
#define DELTA_DIS 1.5f
#define REG_W 0.001f

// scratch (device globals — no allocation allowed)
__device__ float g_cnt_k[MAXB][LBL];          // counts by kernel-region label (incl. 0)
__device__ float g_cnt[MAXB][LBL];            // counts by masked label (incl. 0)
__device__ float g_sum_k[MAXB][LBL][MAXD];    // emb sums by kernel-region label
__device__ float g_sum_v[MAXB][LBL];          // agg-loss value sums by masked label
__device__ float g_mean[MAXB][LBL][MAXD];     // per-label kernel means

__device__ __forceinline__ float wsum(float v) {
#pragma unroll
    for (int o = 16; o; o >>= 1) v += __shfl_xor_sync(0xffffffffu, v, o);
    return v;
}

__global__ void pan_zero_kernel() {
    // zero all accumulators (g_mean is fully overwritten by pan_mean_kernel)
    int i = threadIdx.x;
    float* a = &g_cnt_k[0][0];
    float* b = &g_cnt[0][0];
    float* c = &g_sum_k[0][0][0];
    float* d = &g_sum_v[0][0];
    for (int k = i; k < MAXB * LBL; k += blockDim.x) { a[k] = 0.f; b[k] = 0.f; d[k] = 0.f; }
    for (int k = i; k < MAXB * LBL * MAXD; k += blockDim.x) c[k] = 0.f;
}

// Pass 1: per-pixel segment counts/sums. Per-warp replicated shared histograms.
// layout per warp: [0..31]=cnt, [32..63]=cnt_k, [64..64+4*L)=sum_k
__global__ void pan_accum_kernel(const float* __restrict__ emb,
                                 const int* __restrict__ inst,
                                 const float* __restrict__ ker,
                                 const float* __restrict__ tmk,
                                 int D, int Npix) {
    const int b = blockIdx.y;
    const int w = threadIdx.x >> 5;
    __shared__ float s[8][LBL * 6];
    for (int i = threadIdx.x; i < 8 * LBL * 6; i += blockDim.x)
        (&s[0][0])[i] = 0.f;
    __syncthreads();

    const size_t base = (size_t)b * Npix;
    const float* tm = tmk + base;
    const float* kn = ker + base;
    const int*   ip = inst + base;
    const size_t ebase = (size_t)b * D * Npix;

    for (int i = blockIdx.x * blockDim.x + threadIdx.x; i < Npix;
         i += gridDim.x * blockDim.x) {
        const bool t = tm[i] > 0.5f;
        const bool k = kn[i] > 0.5f;
        const int  v = ip[i];
        const int li = t ? v : 0;
        const int lk = (t && k) ? v : 0;
        atomicAdd(&s[w][li], 1.0f);
        atomicAdd(&s[w][32 + lk], 1.0f);
        if (lk > 0) {
#pragma unroll 4
            for (int d = 0; d < D; ++d) {
                float e = emb[ebase + (size_t)d * Npix + i];
                atomicAdd(&s[w][64 + lk * 4 + d], e);
            }
        }
    }
    __syncthreads();

    for (int idx = threadIdx.x; idx < LBL * 6; idx += blockDim.x) {
        float acc = 0.f;
#pragma unroll
        for (int ww = 0; ww < 8; ++ww) acc += s[ww][idx];
        if (acc != 0.f) {
            if (idx < 32)       atomicAdd(&g_cnt[b][idx], acc);
            else if (idx < 64)  atomicAdd(&g_cnt_k[b][idx - 32], acc);
            else                atomicAdd(&g_sum_k[b][(idx - 64) >> 2][(idx - 64) & 3], acc);
        }
    }
}

__global__ void pan_mean_kernel() {   // grid = B, block = 32
    const int b = blockIdx.x;
    const int l = threadIdx.x;
    const float c = fmaxf(g_cnt_k[b][l], 1.0f);
#pragma unroll
    for (int d = 0; d < MAXD; ++d) {
        float m = (l > 0) ? g_sum_k[b][l][d] / c : 0.0f;  // row 0 forced to 0
        g_mean[b][l][d] = m;
    }
}

// Pass 2: per-pixel aggregation value, accumulated per masked label.
__global__ void pan_agg_kernel(const float* __restrict__ emb,
                               const int* __restrict__ inst,
                               const float* __restrict__ tmk,
                               int D, int Npix) {
    const int b = blockIdx.y;
    const int w = threadIdx.x >> 5;
    __shared__ float sm[LBL][5];     // padded stride-5 to spread banks
    __shared__ float sv[8][LBL];
    for (int i = threadIdx.x; i < LBL * MAXD; i += blockDim.x)
        sm[i >> 2][i & 3] = g_mean[b][i >> 2][i & 3];
    for (int i = threadIdx.x; i < 8 * LBL; i += blockDim.x)
        (&sv[0][0])[i] = 0.f;
    __syncthreads();

    const size_t base = (size_t)b * Npix;
    const float* tm = tmk + base;
    const int*   ip = inst + base;
    const size_t ebase = (size_t)b * D * Npix;

    for (int i = blockIdx.x * blockDim.x + threadIdx.x; i < Npix;
         i += gridDim.x * blockDim.x) {
        const bool t = tm[i] > 0.5f;
        const int  v = ip[i];
        if (t && v > 0) {
            float sq = 0.f;
#pragma unroll 4
            for (int d = 0; d < D; ++d) {
                float e  = emb[ebase + (size_t)d * Npix + i];
                float df = e - sm[v][d];
                sq += df * df;
            }
            float dist = sqrtf(sq);
            float r = fmaxf(dist - DELTA_AGG, 0.0f);
            atomicAdd(&sv[w][v], log1pf(r * r));
        }
    }
    __syncthreads();

    for (int l = threadIdx.x; l < LBL; l += blockDim.x) {
        float acc = 0.f;
#pragma unroll
        for (int ww = 0; ww < 8; ++ww) acc += sv[ww][l];
        if (acc != 0.f) atomicAdd(&g_sum_v[b][l], acc);
    }
}

__global__ void pan_final_kernel(float* __restrict__ out) {  // grid = B, block = 32
    const int b = blockIdx.x;
    const int l = threadIdx.x;
    __shared__ float s_mean[LBL][5];

    float mean[MAXD];
#pragma unroll
    for (int d = 0; d < MAXD; ++d) {
        mean[d] = g_mean[b][l][d];
        s_mean[l][d] = mean[d];
    }
    const float ck = g_cnt_k[b][l];
    const bool present = ck > 0.0f;
    __syncwarp();

    const unsigned pres_mask = __ballot_sync(0xffffffffu, present);
    const int ni = __popc(pres_mask);
    const bool nz = present && (l > 0);
    const unsigned nz_mask = __ballot_sync(0xffffffffu, nz);

    // aggregation term
    float a = nz ? g_sum_v[b][l] / fmaxf(g_cnt[b][l], 1.0f) : 0.0f;

    // regularizer term
    float sq = 0.f;
#pragma unroll
    for (int d = 0; d < MAXD; ++d) sq += mean[d] * mean[d];
    float r = present ? log1pf(sqrtf(sq)) : 0.0f;

    // discrimination term: all ordered pairs of distinct nz labels
    float dsum = 0.f, dcnt = 0.f;
    if (nz) {
#pragma unroll 1
        for (int j = 1; j < LBL; ++j) {
            if (j != l && ((nz_mask >> j) & 1u)) {
                float s = 0.f;
#pragma unroll
                for (int d = 0; d < MAXD; ++d) {
                    float t = mean[d] - s_mean[j][d];
                    s += t * t;
                }
                float pd = sqrtf(s);
                float rr = fmaxf(2.0f * DELTA_DIS - pd, 0.0f);
                dsum += log1pf(rr * rr);
                dcnt += 1.0f;
            }
        }
    }

    a    = wsum(a);
    r    = wsum(r);
    dsum = wsum(dsum);
    dcnt = wsum(dcnt);

    if (l == 0) {
        float l_agg = a / fmaxf((float)(ni - 1), 1.0f);
        float l_dis = (ni > 2) ? dsum / fmaxf(dcnt, 1.0f) : 0.0f;
        float l_reg = r / fmaxf((float)ni, 1.0f) * REG_W;
        float loss = l_agg + l_dis + l_reg;
        out[b] = (ni <= 1) ? 0.0f : loss;
    }
}

extern "C" void kernel_launch(void* const* d_in, const int* in_sizes, int n_in,
                              void* d_out, int out_size) {
    const float* emb  = (const float*)d_in[0];
    const int*   inst = (const int*)d_in[1];
    const float* ker  = (const float*)d_in[2];
    const float* tmk  = (const float*)d_in[3];
    float* out = (float*)d_out;

    const int B = out_size;                       // 8
    const int Npix = in_sizes[1] / B;             // 736*736
    const int D = in_sizes[0] / in_sizes[1];      // 4

    pan_zero_kernel<<<1, 256>>>();

    // ~2048 pixels per block (256 threads x 8 pixels)
    int bx = (Npix + 2047) / 2048;
    dim3 grid(bx, B);

    pan_accum_kernel<<<grid, 256>>>(emb, inst, ker, tmk, D, Npix);
    pan_mean_kernel<<<B, 32>>>();
    pan_agg_kernel<<<grid, 256>>>(emb, inst, tmk, D, Npix);
    pan_final_kernel<<<B, 32>>>(out);
}